// round 9
// baseline (speedup 1.0000x reference)
#include <cuda_runtime.h>
#include <cuda_bf16.h>
#include <math.h>
#include <stdint.h>

#define B_ 16
#define T_ 2000
#define U_ 400
#define D_ 512
#define C_ 4096
#define M_ (B_ * T_)   // 32000
#define NEGF (-1e30f)

// ---------------- device scratch ----------------
__device__ __align__(16) __nv_bfloat16 g_logits[(size_t)M_ * C_];  // 256 MB
__device__ __align__(16) float g_lp[(size_t)2 * B_ * T_ * U_];     // 102 MB
__device__ float g_loss[2 * B_];
__device__ __align__(16) __nv_bfloat16 g_xb[(size_t)M_ * D_];
__device__ __align__(16) __nv_bfloat16 g_Wb[(size_t)D_ * C_];

__device__ __forceinline__ float laef(float a, float b) {
    float mx = fmaxf(a, b);
    float d  = fminf(a, b) - mx;
    return mx + __logf(1.0f + __expf(d));
}

// ---------------- cp.async helpers ----------------
__device__ __forceinline__ void cpa16(uint32_t dst, const void* src) {
    asm volatile("cp.async.cg.shared.global [%0], [%1], 16;\n"
                 :: "r"(dst), "l"(src));
}
__device__ __forceinline__ void cpa_commit() {
    asm volatile("cp.async.commit_group;\n" ::: "memory");
}
template <int N>
__device__ __forceinline__ void cpa_wait() {
    asm volatile("cp.async.wait_group %0;\n" :: "n"(N) : "memory");
}

// ---------------- 0) fp32 -> bf16 conversion ----------------
__device__ __forceinline__ void cvt8(const float* __restrict__ in,
                                     __nv_bfloat16* __restrict__ out, int i) {
    const float4* p = (const float4*)in + (size_t)i * 2;
    float4 v0 = p[0], v1 = p[1];
    __nv_bfloat162 b0 = __floats2bfloat162_rn(v0.x, v0.y);
    __nv_bfloat162 b1 = __floats2bfloat162_rn(v0.z, v0.w);
    __nv_bfloat162 b2 = __floats2bfloat162_rn(v1.x, v1.y);
    __nv_bfloat162 b3 = __floats2bfloat162_rn(v1.z, v1.w);
    uint4 o;
    o.x = *reinterpret_cast<unsigned*>(&b0);
    o.y = *reinterpret_cast<unsigned*>(&b1);
    o.z = *reinterpret_cast<unsigned*>(&b2);
    o.w = *reinterpret_cast<unsigned*>(&b3);
    *((uint4*)out + i) = o;
}

#define NXC ((M_ * D_) / 8)
#define NWC ((D_ * C_) / 8)
__global__ __launch_bounds__(256) void cvt_all_kernel(
    const float* __restrict__ x, const float* __restrict__ W) {
    int i = blockIdx.x * 256 + threadIdx.x;
    if (i < NXC) cvt8(x, g_xb, i);
    else if (i < NXC + NWC) cvt8(W, g_Wb, i - NXC);
}

__global__ void noop_kernel() {}

// ---------------- 1) bf16 GEMM v3: 128x256 block, 64x64 warp tiles --------
#define BK 32
#define STG 3
#define PA 8                 // A pitch 40 elems (80 B)
#define PB 8                 // B pitch 264 elems (528 B)
#define BN 256

__global__ __launch_bounds__(256) void gemm_bf16_kernel(const float* __restrict__ bias)
{
    __shared__ __nv_bfloat16 As[STG][128][BK + PA];   // 30720 B
    __shared__ __nv_bfloat16 Bs[STG][BK][BN + PB];    // 50688 B

    const int tid = threadIdx.x;
    const int wid = tid >> 5, lane = tid & 31;
    const int bm = blockIdx.y, bn = blockIdx.x;
    const int wm = wid & 1, wn = wid >> 1;   // 2 (m) x 4 (n) warps, each 64x64

    const __nv_bfloat16* gAr = g_xb + (size_t)(bm * 128) * D_;
    const __nv_bfloat16* gBr = g_Wb + bn * BN;

    const uint32_t aBase = (uint32_t)__cvta_generic_to_shared(&As[0][0][0]);
    const uint32_t bBase = (uint32_t)__cvta_generic_to_shared(&Bs[0][0][0]);
    const uint32_t AstgSz = sizeof(As[0]);
    const uint32_t BstgSz = sizeof(Bs[0]);

    // per stage: A = 512 16B-chunks (2/thread), B = 1024 chunks (4/thread)
    auto issue = [&](int s, int k0) {
#pragma unroll
        for (int l = 0; l < 2; l++) {
            int c = tid * 2 + l;
            int ar = c >> 2, ac = (c & 3) * 8;
            cpa16(aBase + s * AstgSz + (ar * (BK + PA) + ac) * 2,
                  gAr + (size_t)ar * D_ + k0 + ac);
        }
#pragma unroll
        for (int l = 0; l < 4; l++) {
            int c = tid * 4 + l;
            int br = c >> 5, bc = (c & 31) * 8;
            cpa16(bBase + s * BstgSz + (br * (BN + PB) + bc) * 2,
                  gBr + (size_t)(k0 + br) * C_ + bc);
        }
    };

    const int aRow = wm * 64 + (lane & 7) + ((lane >> 3) & 1) * 8;  // + mt*16
    const int aColHalf = ((lane >> 4) & 1) * 8;                     // + ks*16
    const int bRowHalf = (lane & 7) + ((lane >> 3) & 1) * 8;        // + ks*16
    const int bColBase = wn * 64 + ((lane >> 4) & 1) * 8;           // + pr*16

    float acc[4][8][4];
#pragma unroll
    for (int mt = 0; mt < 4; mt++)
#pragma unroll
        for (int nt = 0; nt < 8; nt++)
#pragma unroll
            for (int j = 0; j < 4; j++) acc[mt][nt][j] = 0.0f;

    issue(0, 0);  cpa_commit();
    issue(1, BK); cpa_commit();

    const int NKT = D_ / BK;   // 16
#pragma unroll 1
    for (int kt = 0; kt < NKT; kt++) {
        if (kt + 2 < NKT) issue((kt + 2) % STG, (kt + 2) * BK);
        cpa_commit();
        cpa_wait<2>();
        __syncthreads();

        const int p = kt % STG;
#pragma unroll
        for (int ks = 0; ks < 2; ks++) {
            uint32_t a[4][4], b[4][4];
#pragma unroll
            for (int mt = 0; mt < 4; mt++) {
                uint32_t addr = aBase + p * AstgSz +
                    ((aRow + mt * 16) * (BK + PA) + ks * 16 + aColHalf) * 2;
                asm volatile("ldmatrix.sync.aligned.m8n8.x4.shared.b16 {%0,%1,%2,%3}, [%4];"
                    : "=r"(a[mt][0]), "=r"(a[mt][1]), "=r"(a[mt][2]), "=r"(a[mt][3])
                    : "r"(addr));
            }
#pragma unroll
            for (int pr = 0; pr < 4; pr++) {
                uint32_t addr = bBase + p * BstgSz +
                    ((ks * 16 + bRowHalf) * (BN + PB) + bColBase + pr * 16) * 2;
                asm volatile("ldmatrix.sync.aligned.m8n8.x4.trans.shared.b16 {%0,%1,%2,%3}, [%4];"
                    : "=r"(b[pr][0]), "=r"(b[pr][1]), "=r"(b[pr][2]), "=r"(b[pr][3])
                    : "r"(addr));
            }
#pragma unroll
            for (int mt = 0; mt < 4; mt++)
#pragma unroll
                for (int nt = 0; nt < 8; nt++) {
                    uint32_t b0 = b[nt >> 1][(nt & 1) * 2 + 0];
                    uint32_t b1 = b[nt >> 1][(nt & 1) * 2 + 1];
                    asm volatile(
                        "mma.sync.aligned.m16n8k16.row.col.f32.bf16.bf16.f32 "
                        "{%0,%1,%2,%3}, {%4,%5,%6,%7}, {%8,%9}, {%0,%1,%2,%3};"
                        : "+f"(acc[mt][nt][0]), "+f"(acc[mt][nt][1]),
                          "+f"(acc[mt][nt][2]), "+f"(acc[mt][nt][3])
                        : "r"(a[mt][0]), "r"(a[mt][1]), "r"(a[mt][2]), "r"(a[mt][3]),
                          "r"(b0), "r"(b1));
                }
        }
        __syncthreads();
    }

    // epilogue: add bias, pack bf16x2, store
    const int tig = lane & 3, grp = lane >> 2;
#pragma unroll
    for (int mt = 0; mt < 4; mt++) {
        int row0 = bm * 128 + wm * 64 + mt * 16 + grp;
#pragma unroll
        for (int nt = 0; nt < 8; nt++) {
            int col = bn * BN + wn * 64 + nt * 8 + 2 * tig;
            float b0v = bias[col], b1v = bias[col + 1];
            __nv_bfloat162 p0 = __floats2bfloat162_rn(acc[mt][nt][0] + b0v,
                                                      acc[mt][nt][1] + b1v);
            __nv_bfloat162 p1 = __floats2bfloat162_rn(acc[mt][nt][2] + b0v,
                                                      acc[mt][nt][3] + b1v);
            *(__nv_bfloat162*)&g_logits[(size_t)row0 * C_ + col] = p0;
            *(__nv_bfloat162*)&g_logits[(size_t)(row0 + 8) * C_ + col] = p1;
        }
    }
}

// ---------------- 2) fused logsumexp + gather ----------------
__global__ __launch_bounds__(256) void lse_gather_kernel(
    const int* __restrict__ tgt1, const int* __restrict__ tgt2,
    const int* __restrict__ act_lens,
    const int* __restrict__ tl1, const int* __restrict__ tl2)
{
    int t = blockIdx.x, b = blockIdx.y;
    int alen = act_lens[b];
    if (t >= alen) return;

    __shared__ uint16_t srow[C_];    // 8 KB
    __shared__ float red[256];
    int tid = threadIdx.x;
    int row = b * T_ + t;

    const uint4* rp = (const uint4*)(g_logits + (size_t)row * C_);
    uint4 v0 = rp[tid], v1 = rp[tid + 256];
    ((uint4*)srow)[tid] = v0;
    ((uint4*)srow)[tid + 256] = v1;

    uint32_t w[8] = {v0.x, v0.y, v0.z, v0.w, v1.x, v1.y, v1.z, v1.w};
    float f[16];
#pragma unroll
    for (int i = 0; i < 8; i++) {
        float2 p = __bfloat1622float2(*reinterpret_cast<__nv_bfloat162*>(&w[i]));
        f[2 * i] = p.x; f[2 * i + 1] = p.y;
    }

    float mx = -1e30f;
#pragma unroll
    for (int i = 0; i < 16; i++) mx = fmaxf(mx, f[i]);
    red[tid] = mx;
    __syncthreads();
    for (int s = 128; s > 0; s >>= 1) {
        if (tid < s) red[tid] = fmaxf(red[tid], red[tid + s]);
        __syncthreads();
    }
    mx = red[0];
    __syncthreads();

    float sum = 0.0f;
#pragma unroll
    for (int i = 0; i < 16; i++) sum += __expf(f[i] - mx);
    red[tid] = sum;
    __syncthreads();
    for (int s = 128; s > 0; s >>= 1) {
        if (tid < s) red[tid] += red[tid + s];
        __syncthreads();
    }
    float lse = mx + __logf(red[0]);

#pragma unroll
    for (int s = 0; s < 2; s++) {
        const int* tgt = (s ? tgt2 : tgt1) + b * U_;
        int tlen = (s ? tl2 : tl1)[b];
        float* lprow = g_lp + ((size_t)(s * B_ + b) * T_ + t) * U_;
#pragma unroll
        for (int u = tid; u < U_; u += 256) {
            float val = NEGF;
            if (u < tlen) {
                uint16_t raw = srow[__ldg(tgt + u)];
                val = __bfloat162float(*reinterpret_cast<__nv_bfloat16*>(&raw)) - lse;
            }
            lprow[u] = val;
        }
    }
}

// ---------------- 3) alpha v5: branchless inner loop, cp.async ring -------
#define RD 8        // ring depth (rows)
#define SLOTF 512   // floats per slot

__global__ __launch_bounds__(128) void alpha_kernel(
    const int* __restrict__ act_lens,
    const int* __restrict__ tl1, const int* __restrict__ tl2)
{
    int chain = blockIdx.x;
    int s = chain >> 4, b = chain & 15;
    int tlen = (s ? tl2 : tl1)[b];
    int alen = act_lens[b];          // >= 1000
    int tid = threadIdx.x, w = tid >> 5, lane = tid & 31;
    const float* lp = g_lp + (size_t)chain * T_ * U_;

    __shared__ __align__(16) float ring[RD][SLOTF];   // 16 KB
    __shared__ float bnd[2][5][4];   // [parity][warp+1][band]; [.][0][.] = ghost

    const uint32_t ringBase = (uint32_t)__cvta_generic_to_shared(&ring[0][0]);

    // pre-fill ring cols 400..511 with NEGF (cp.async never writes them)
    if (tid >= 100) {
        float4 nf = make_float4(NEGF, NEGF, NEGF, NEGF);
#pragma unroll
        for (int r = 0; r < RD; r++)
            *(float4*)&ring[r][tid * 4] = nf;
    }
    if (tid == 0) { bnd[0][0][0] = NEGF; bnd[1][0][0] = NEGF; }

    float a[4];
#pragma unroll
    for (int i = 0; i < 4; i++) {
        int u = i * 128 + tid;
        float v = (u < U_) ? lp[u] : NEGF;
        a[i] = v + ((u == 0) ? 0.0f : NEGF);
    }

    const int uoff = (tid < 100) ? tid * 4 : 0;   // clamped: dup writes identical

#pragma unroll
    for (int r = 1; r < RD; r++) {
        cpa16(ringBase + (r * SLOTF + uoff) * 4, lp + (size_t)r * U_ + uoff);
        cpa_commit();
    }
    __syncthreads();

#pragma unroll 1
    for (int t = 1; t < alen; t++) {
        const int p = t & 1;
        if (lane == 31) {
#pragma unroll
            for (int i = 0; i < 4; i++) bnd[p][w + 1][i] = a[i];
            if (w == 3) {
#pragma unroll
                for (int i = 0; i < 3; i++) bnd[p][0][i + 1] = a[i];
            }
        }
        cpa_wait<RD - 2>();
        __syncthreads();

        int tn = min(t + RD - 1, alen - 1);
        cpa16(ringBase + (((tn & (RD - 1)) * SLOTF) + uoff) * 4,
              lp + (size_t)tn * U_ + uoff);
        cpa_commit();

        const float* cs = ring[t & (RD - 1)];
#pragma unroll
        for (int i = 0; i < 4; i++) {
            float up = __shfl_up_sync(0xffffffffu, a[i], 1);
            float bv = bnd[p][w][i];
            up = (lane == 0) ? bv : up;
            a[i] = laef(a[i], up) + cs[i * 128 + tid];
        }
    }

    int ustar = tlen - 1;
    int ui = ustar >> 7, ut = ustar & 127;
    if (tid == ut) {
        float v = (ui == 0) ? a[0] : (ui == 1) ? a[1] : (ui == 2) ? a[2] : a[3];
        g_loss[chain] = -v;
    }
}

// ---------------- 4) final reduction ----------------
__global__ void loss_kernel(float* out)
{
    if (threadIdx.x == 0) {
        float l1 = 0.0f, l2 = 0.0f;
        for (int i = 0; i < 16; i++) { l1 += g_loss[i]; l2 += g_loss[16 + i]; }
        l1 *= (1.0f / 16.0f);
        l2 *= (1.0f / 16.0f);
        out[0] = l1 - 0.5f * l2;
        out[1] = l1;
        out[2] = l2;
    }
}

// ---------------- launch ----------------
extern "C" void kernel_launch(void* const* d_in, const int* in_sizes, int n_in,
                              void* d_out, int out_size)
{
    const float* x    = (const float*)d_in[0];
    const float* W    = (const float*)d_in[1];
    const float* bias = (const float*)d_in[2];
    const int* tgt1   = (const int*)d_in[3];
    const int* tgt2   = (const int*)d_in[4];
    const int* alen   = (const int*)d_in[5];
    const int* tl1    = (const int*)d_in[6];
    const int* tl2    = (const int*)d_in[7];
    float* out = (float*)d_out;

    cvt_all_kernel<<<(NXC + NWC + 255) / 256, 256>>>(x, W);   // launch 1
    noop_kernel<<<1, 32>>>();                                  // launch 2
    noop_kernel<<<1, 32>>>();                                  // launch 3

    dim3 ggrid(C_ / BN, M_ / 128);                             // launch 4 = GEMM (profiled)
    gemm_bf16_kernel<<<ggrid, 256>>>(bias);

    dim3 lgrid(T_, B_);
    lse_gather_kernel<<<lgrid, 256>>>(tgt1, tgt2, alen, tl1, tl2);

    alpha_kernel<<<2 * B_, 128>>>(alen, tl1, tl2);

    loss_kernel<<<1, 32>>>(out);
}

// round 10
// speedup vs baseline: 1.1468x; 1.1468x over previous
#include <cuda_runtime.h>
#include <cuda_bf16.h>
#include <math.h>
#include <stdint.h>

#define B_ 16
#define T_ 2000
#define U_ 400
#define D_ 512
#define C_ 4096
#define M_ (B_ * T_)   // 32000
#define NEGF (-1e30f)

// ---------------- device scratch ----------------
__device__ __align__(16) __nv_bfloat16 g_logits[(size_t)M_ * C_];  // 256 MB
__device__ __align__(16) float g_lp[(size_t)2 * B_ * T_ * U_];     // 102 MB
__device__ float g_loss[2 * B_];
__device__ __align__(16) __nv_bfloat16 g_xb[(size_t)M_ * D_];
__device__ __align__(16) __nv_bfloat16 g_Wb[(size_t)D_ * C_];

__device__ __forceinline__ float laef(float a, float b) {
    float mx = fmaxf(a, b);
    float d  = fminf(a, b) - mx;
    return mx + __logf(1.0f + __expf(d));
}

// ---------------- cp.async helpers ----------------
__device__ __forceinline__ void cpa16(uint32_t dst, const void* src) {
    asm volatile("cp.async.cg.shared.global [%0], [%1], 16;\n"
                 :: "r"(dst), "l"(src));
}
__device__ __forceinline__ void cpa_commit() {
    asm volatile("cp.async.commit_group;\n" ::: "memory");
}
template <int N>
__device__ __forceinline__ void cpa_wait() {
    asm volatile("cp.async.wait_group %0;\n" :: "n"(N) : "memory");
}

// ---------------- 0) fp32 -> bf16 conversion ----------------
__device__ __forceinline__ void cvt8(const float* __restrict__ in,
                                     __nv_bfloat16* __restrict__ out, int i) {
    const float4* p = (const float4*)in + (size_t)i * 2;
    float4 v0 = p[0], v1 = p[1];
    __nv_bfloat162 b0 = __floats2bfloat162_rn(v0.x, v0.y);
    __nv_bfloat162 b1 = __floats2bfloat162_rn(v0.z, v0.w);
    __nv_bfloat162 b2 = __floats2bfloat162_rn(v1.x, v1.y);
    __nv_bfloat162 b3 = __floats2bfloat162_rn(v1.z, v1.w);
    uint4 o;
    o.x = *reinterpret_cast<unsigned*>(&b0);
    o.y = *reinterpret_cast<unsigned*>(&b1);
    o.z = *reinterpret_cast<unsigned*>(&b2);
    o.w = *reinterpret_cast<unsigned*>(&b3);
    *((uint4*)out + i) = o;
}

#define NXC ((M_ * D_) / 8)
#define NWC ((D_ * C_) / 8)
__global__ __launch_bounds__(256) void cvt_all_kernel(
    const float* __restrict__ x, const float* __restrict__ W) {
    int i = blockIdx.x * 256 + threadIdx.x;
    if (i < NXC) cvt8(x, g_xb, i);
    else if (i < NXC + NWC) cvt8(W, g_Wb, i - NXC);
}

// ---------------- 1) bf16 GEMM: 128x128 block, STG=4, single-sync --------
#define BK 32
#define STG 4
#define PA 8                 // A pitch 40 elems (80 B)
#define PB 8                 // B pitch 136 elems (272 B)

__global__ __launch_bounds__(256) void gemm_bf16_kernel(const float* __restrict__ bias)
{
    __shared__ __nv_bfloat16 As[STG][128][BK + PA];   // 40960 B
    __shared__ __nv_bfloat16 Bs[STG][BK][128 + PB];   // 34816 B

    const int tid = threadIdx.x;
    const int wid = tid >> 5, lane = tid & 31;
    const int bm = blockIdx.y, bn = blockIdx.x;
    const int wm = wid & 1, wn = wid >> 1;   // 2 (m) x 4 (n) warps, each 64x32

    const __nv_bfloat16* gAr = g_xb + (size_t)(bm * 128) * D_;
    const __nv_bfloat16* gBr = g_Wb + bn * 128;

    const uint32_t aBase = (uint32_t)__cvta_generic_to_shared(&As[0][0][0]);
    const uint32_t bBase = (uint32_t)__cvta_generic_to_shared(&Bs[0][0][0]);
    const uint32_t AstgSz = sizeof(As[0]);
    const uint32_t BstgSz = sizeof(Bs[0]);

    auto issue = [&](int s, int k0) {
#pragma unroll
        for (int l = 0; l < 2; l++) {
            int c = tid * 2 + l;
            int ar = c >> 2, ac = (c & 3) * 8;
            cpa16(aBase + s * AstgSz + (ar * (BK + PA) + ac) * 2,
                  gAr + (size_t)ar * D_ + k0 + ac);
        }
#pragma unroll
        for (int l = 0; l < 2; l++) {
            int c = tid * 2 + l;
            int br = c >> 4, bc = (c & 15) * 8;
            cpa16(bBase + s * BstgSz + (br * (128 + PB) + bc) * 2,
                  gBr + (size_t)(k0 + br) * C_ + bc);
        }
    };

    const int aRow = wm * 64 + (lane & 7) + ((lane >> 3) & 1) * 8;
    const int aColHalf = ((lane >> 4) & 1) * 8;
    const int bRowHalf = (lane & 7) + ((lane >> 3) & 1) * 8;
    const int bColBase = wn * 32 + ((lane >> 4) & 1) * 8;

    float acc[4][4][4];
#pragma unroll
    for (int mt = 0; mt < 4; mt++)
#pragma unroll
        for (int nt = 0; nt < 4; nt++)
#pragma unroll
            for (int j = 0; j < 4; j++) acc[mt][nt][j] = 0.0f;

    issue(0, 0);      cpa_commit();
    issue(1, BK);     cpa_commit();
    issue(2, 2 * BK); cpa_commit();

    const int NKT = D_ / BK;   // 16
#pragma unroll 1
    for (int kt = 0; kt < NKT; kt++) {
        cpa_wait<2>();            // stage kt landed
        __syncthreads();          // also protects slot (kt+3)%4 = (kt-1)%4

        if (kt + 3 < NKT) issue((kt + 3) % STG, (kt + 3) * BK);
        cpa_commit();

        const int p = kt % STG;
#pragma unroll
        for (int ks = 0; ks < 2; ks++) {
            uint32_t a[4][4], b[2][4];
#pragma unroll
            for (int mt = 0; mt < 4; mt++) {
                uint32_t addr = aBase + p * AstgSz +
                    ((aRow + mt * 16) * (BK + PA) + ks * 16 + aColHalf) * 2;
                asm volatile("ldmatrix.sync.aligned.m8n8.x4.shared.b16 {%0,%1,%2,%3}, [%4];"
                    : "=r"(a[mt][0]), "=r"(a[mt][1]), "=r"(a[mt][2]), "=r"(a[mt][3])
                    : "r"(addr));
            }
#pragma unroll
            for (int pr = 0; pr < 2; pr++) {
                uint32_t addr = bBase + p * BstgSz +
                    ((ks * 16 + bRowHalf) * (128 + PB) + bColBase + pr * 16) * 2;
                asm volatile("ldmatrix.sync.aligned.m8n8.x4.trans.shared.b16 {%0,%1,%2,%3}, [%4];"
                    : "=r"(b[pr][0]), "=r"(b[pr][1]), "=r"(b[pr][2]), "=r"(b[pr][3])
                    : "r"(addr));
            }
#pragma unroll
            for (int mt = 0; mt < 4; mt++)
#pragma unroll
                for (int nt = 0; nt < 4; nt++) {
                    uint32_t b0 = b[nt >> 1][(nt & 1) * 2 + 0];
                    uint32_t b1 = b[nt >> 1][(nt & 1) * 2 + 1];
                    asm volatile(
                        "mma.sync.aligned.m16n8k16.row.col.f32.bf16.bf16.f32 "
                        "{%0,%1,%2,%3}, {%4,%5,%6,%7}, {%8,%9}, {%0,%1,%2,%3};"
                        : "+f"(acc[mt][nt][0]), "+f"(acc[mt][nt][1]),
                          "+f"(acc[mt][nt][2]), "+f"(acc[mt][nt][3])
                        : "r"(a[mt][0]), "r"(a[mt][1]), "r"(a[mt][2]), "r"(a[mt][3]),
                          "r"(b0), "r"(b1));
                }
        }
    }

    const int tig = lane & 3, grp = lane >> 2;
#pragma unroll
    for (int mt = 0; mt < 4; mt++) {
        int row0 = bm * 128 + wm * 64 + mt * 16 + grp;
#pragma unroll
        for (int nt = 0; nt < 4; nt++) {
            int col = bn * 128 + wn * 32 + nt * 8 + 2 * tig;
            float b0v = bias[col], b1v = bias[col + 1];
            __nv_bfloat162 p0 = __floats2bfloat162_rn(acc[mt][nt][0] + b0v,
                                                      acc[mt][nt][1] + b1v);
            __nv_bfloat162 p1 = __floats2bfloat162_rn(acc[mt][nt][2] + b0v,
                                                      acc[mt][nt][3] + b1v);
            *(__nv_bfloat162*)&g_logits[(size_t)row0 * C_ + col] = p0;
            *(__nv_bfloat162*)&g_logits[(size_t)(row0 + 8) * C_ + col] = p1;
        }
    }
}

// ---------------- 2) fused logsumexp + gather ----------------
__global__ __launch_bounds__(256) void lse_gather_kernel(
    const int* __restrict__ tgt1, const int* __restrict__ tgt2,
    const int* __restrict__ act_lens,
    const int* __restrict__ tl1, const int* __restrict__ tl2)
{
    int t = blockIdx.x, b = blockIdx.y;
    int alen = act_lens[b];
    if (t >= alen) return;

    __shared__ uint16_t srow[C_];    // 8 KB
    __shared__ float red[256];
    int tid = threadIdx.x;
    int row = b * T_ + t;

    const uint4* rp = (const uint4*)(g_logits + (size_t)row * C_);
    uint4 v0 = rp[tid], v1 = rp[tid + 256];
    ((uint4*)srow)[tid] = v0;
    ((uint4*)srow)[tid + 256] = v1;

    uint32_t w[8] = {v0.x, v0.y, v0.z, v0.w, v1.x, v1.y, v1.z, v1.w};
    float f[16];
#pragma unroll
    for (int i = 0; i < 8; i++) {
        float2 p = __bfloat1622float2(*reinterpret_cast<__nv_bfloat162*>(&w[i]));
        f[2 * i] = p.x; f[2 * i + 1] = p.y;
    }

    float mx = -1e30f;
#pragma unroll
    for (int i = 0; i < 16; i++) mx = fmaxf(mx, f[i]);
    red[tid] = mx;
    __syncthreads();
    for (int s = 128; s > 0; s >>= 1) {
        if (tid < s) red[tid] = fmaxf(red[tid], red[tid + s]);
        __syncthreads();
    }
    mx = red[0];
    __syncthreads();

    float sum = 0.0f;
#pragma unroll
    for (int i = 0; i < 16; i++) sum += __expf(f[i] - mx);
    red[tid] = sum;
    __syncthreads();
    for (int s = 128; s > 0; s >>= 1) {
        if (tid < s) red[tid] += red[tid + s];
        __syncthreads();
    }
    float lse = mx + __logf(red[0]);

#pragma unroll
    for (int s = 0; s < 2; s++) {
        const int* tgt = (s ? tgt2 : tgt1) + b * U_;
        int tlen = (s ? tl2 : tl1)[b];
        float* lprow = g_lp + ((size_t)(s * B_ + b) * T_ + t) * U_;
#pragma unroll
        for (int u = tid; u < U_; u += 256) {
            float val = NEGF;
            if (u < tlen) {
                uint16_t raw = srow[__ldg(tgt + u)];
                val = __bfloat162float(*reinterpret_cast<__nv_bfloat16*>(&raw)) - lse;
            }
            lprow[u] = val;
        }
    }
}

// ---------------- 3) alpha v6: register c-prefetch, branchless -----------
#define RD 8        // ring depth (rows)
#define SLOTF 512   // floats per slot

__global__ __launch_bounds__(128) void alpha_kernel(
    const int* __restrict__ act_lens,
    const int* __restrict__ tl1, const int* __restrict__ tl2)
{
    int chain = blockIdx.x;
    int s = chain >> 4, b = chain & 15;
    int tlen = (s ? tl2 : tl1)[b];
    int alen = act_lens[b];          // >= 1000
    int tid = threadIdx.x, w = tid >> 5, lane = tid & 31;
    const float* lp = g_lp + (size_t)chain * T_ * U_;

    __shared__ __align__(16) float ring[RD][SLOTF];   // 16 KB
    __shared__ float bnd[2][5][4];   // [parity][warp+1][band]; [.][0][.] = ghost

    const uint32_t ringBase = (uint32_t)__cvta_generic_to_shared(&ring[0][0]);

    // pre-fill ring cols 400..511 with NEGF (cp.async never writes them)
    if (tid >= 100) {
        float4 nf = make_float4(NEGF, NEGF, NEGF, NEGF);
#pragma unroll
        for (int r = 0; r < RD; r++)
            *(float4*)&ring[r][tid * 4] = nf;
    }
    if (tid == 0) { bnd[0][0][0] = NEGF; bnd[1][0][0] = NEGF; }

    float a[4];
#pragma unroll
    for (int i = 0; i < 4; i++) {
        int u = i * 128 + tid;
        float v = (u < U_) ? lp[u] : NEGF;
        a[i] = v + ((u == 0) ? 0.0f : NEGF);
    }

    const int uoff = (tid < 100) ? tid * 4 : 0;   // clamped: dup writes identical

    // prologue: rows 1..RD-1 into slots 1..RD-1 (one commit group per row)
#pragma unroll
    for (int r = 1; r < RD; r++) {
        cpa16(ringBase + (r * SLOTF + uoff) * 4, lp + (size_t)r * U_ + uoff);
        cpa_commit();
    }
    cpa_wait<RD - 2>();    // row 1 landed
    __syncthreads();       // + NEGF fill, ghost init visible

    // preload c = row 1 into registers
    float c[4];
#pragma unroll
    for (int i = 0; i < 4; i++) c[i] = ring[1][i * 128 + tid];

#pragma unroll 1
    for (int t = 1; t < alen; t++) {
        const int p = t & 1;
        if (lane == 31) {
#pragma unroll
            for (int i = 0; i < 4; i++) bnd[p][w + 1][i] = a[i];
            if (w == 3) {
#pragma unroll
                for (int i = 0; i < 3; i++) bnd[p][0][i + 1] = a[i];
            }
        }
        cpa_wait<RD - 3>();       // rows <= t+1 landed
        __syncthreads();          // bnd + ring visible

        // issue row t+RD-1 into slot (t-1)%RD (last read at iter t-2)
        int tn = min(t + RD - 1, alen - 1);
        cpa16(ringBase + (((tn & (RD - 1)) * SLOTF) + uoff) * 4,
              lp + (size_t)tn * U_ + uoff);
        cpa_commit();

        // prefetch next step's c (off the dependent path)
        const float* csn = ring[(t + 1) & (RD - 1)];
        float cn[4];
#pragma unroll
        for (int i = 0; i < 4; i++) cn[i] = csn[i * 128 + tid];

#pragma unroll
        for (int i = 0; i < 4; i++) {
            float up = __shfl_up_sync(0xffffffffu, a[i], 1);
            float bv = bnd[p][w][i];           // uniform LDS
            up = (lane == 0) ? bv : up;        // select, no branch
            a[i] = laef(a[i], up) + c[i];
        }
#pragma unroll
        for (int i = 0; i < 4; i++) c[i] = cn[i];
    }

    int ustar = tlen - 1;
    int ui = ustar >> 7, ut = ustar & 127;
    if (tid == ut) {
        float v = (ui == 0) ? a[0] : (ui == 1) ? a[1] : (ui == 2) ? a[2] : a[3];
        g_loss[chain] = -v;
    }
}

// ---------------- 4) final reduction ----------------
__global__ void loss_kernel(float* out)
{
    if (threadIdx.x == 0) {
        float l1 = 0.0f, l2 = 0.0f;
        for (int i = 0; i < 16; i++) { l1 += g_loss[i]; l2 += g_loss[16 + i]; }
        l1 *= (1.0f / 16.0f);
        l2 *= (1.0f / 16.0f);
        out[0] = l1 - 0.5f * l2;
        out[1] = l1;
        out[2] = l2;
    }
}

// ---------------- launch ----------------
extern "C" void kernel_launch(void* const* d_in, const int* in_sizes, int n_in,
                              void* d_out, int out_size)
{
    const float* x    = (const float*)d_in[0];
    const float* W    = (const float*)d_in[1];
    const float* bias = (const float*)d_in[2];
    const int* tgt1   = (const int*)d_in[3];
    const int* tgt2   = (const int*)d_in[4];
    const int* alen   = (const int*)d_in[5];
    const int* tl1    = (const int*)d_in[6];
    const int* tl2    = (const int*)d_in[7];
    float* out = (float*)d_out;

    cvt_all_kernel<<<(NXC + NWC + 255) / 256, 256>>>(x, W);   // launch 1

    dim3 ggrid(C_ / 128, M_ / 128);                           // launch 2
    gemm_bf16_kernel<<<ggrid, 256>>>(bias);

    dim3 lgrid(T_, B_);                                       // launch 3
    lse_gather_kernel<<<lgrid, 256>>>(tgt1, tgt2, alen, tl1, tl2);

    alpha_kernel<<<2 * B_, 128>>>(alen, tl1, tl2);            // launch 4 = profiled

    loss_kernel<<<1, 32>>>(out);                              // launch 5
}